// round 11
// baseline (speedup 1.0000x reference)
#include <cuda_runtime.h>
#include <cuda_fp16.h>
#include <math.h>

#define S_LEN 2048
#define E_DIM 1024
#define NH    8
#define DH    128
#define EPS_F 1e-6f

// ---------------- scratch ----------------
__device__ float g_part[3][16][S_LEN];  // gate partials
__device__ float g_M [NH][S_LEN];       // prefix max of a[j] = i_pre - cum
__device__ float g_n2[NH][S_LEN];       // exp(-(cum+M))
__device__ float g_E [NH][S_LEN];       // exp(a[j] - T_tile(j))
__device__ float g_T [NH][S_LEN/128];   // per-128-tile max of a
__device__ float g_Op[2][S_LEN * E_DIM];// partial O (unnormalized), per j-half
__device__ float g_rsp[2][NH][S_LEN];   // partial rowsums, per j-half
__device__ __half g_kh[S_LEN * E_DIM];  // fp16 K with E folded in
__device__ __half g_vh[S_LEN * E_DIM];  // fp16 V

__device__ __forceinline__ void mma16(float* d, const unsigned* a, const unsigned* b) {
    asm volatile("mma.sync.aligned.m16n8k16.row.col.f32.f16.f16.f32 "
        "{%0,%1,%2,%3}, {%4,%5,%6,%7}, {%8,%9}, {%0,%1,%2,%3};"
        : "+f"(d[0]), "+f"(d[1]), "+f"(d[2]), "+f"(d[3])
        : "r"(a[0]), "r"(a[1]), "r"(a[2]), "r"(a[3]), "r"(b[0]), "r"(b[1]));
}
__device__ __forceinline__ void ldsm4t(unsigned* r, unsigned addr) {
    asm volatile("ldmatrix.sync.aligned.m8n8.x4.trans.shared.b16 {%0,%1,%2,%3}, [%4];"
        : "=r"(r[0]), "=r"(r[1]), "=r"(r[2]), "=r"(r[3]) : "r"(addr));
}
__device__ __forceinline__ void cpa16(unsigned dst, const __half* src) {
    asm volatile("cp.async.cg.shared.global [%0], [%1], 16;" :: "r"(dst), "l"(src));
}
__device__ __forceinline__ void cpa_commit() {
    asm volatile("cp.async.commit_group;");
}
template<int N> __device__ __forceinline__ void cpa_wait() {
    asm volatile("cp.async.wait_group %0;" :: "n"(N));
}

// =================================================================
// Kernel 1: gate partials (R6 variant — best measured).
// =================================================================
__global__ void __launch_bounds__(256, 2)
gate_kernel(const float* __restrict__ q,
            const float* __restrict__ k,
            const float* __restrict__ v,
            const float* __restrict__ Wi,
            const float* __restrict__ Wf) {
    extern __shared__ float gs[];
    float* sW  = gs;                  // [1024][16]
    float* sX  = sW + 1024 * 16;      // per warp [16][33]
    float* red = sX + 8 * 16 * 33;    // [8*32][20]

    int tid = threadIdx.x, w = tid >> 5, lane = tid & 31;
    int sl = blockIdx.y;
    const float* x = (sl == 0) ? q : (sl == 1) ? k : v;

    for (int i = tid; i < 1024 * 8; i += 256) {
        int e = i >> 3, g = i & 7;
        sW[e * 16 + g]     = Wi[(sl * 1024 + e) * 8 + g];
        sW[e * 16 + 8 + g] = Wf[(sl * 1024 + e) * 8 + g];
    }
    __syncthreads();

    int r0 = blockIdx.x * 16;
    int e_off = w * 128;
    int rr = lane & 15, hh = lane >> 4;
    const float* xb = x + r0 * E_DIM + e_off;
    float* sXw = sX + w * 16 * 33;

    float acc[16];
    #pragma unroll
    for (int g = 0; g < 16; ++g) acc[g] = 0.f;

    float buf[16];
    #pragma unroll
    for (int r = 0; r < 16; ++r) buf[r] = xb[r * E_DIM + lane];

    #pragma unroll
    for (int c = 0; c < 4; ++c) {
        __syncwarp();
        #pragma unroll
        for (int r = 0; r < 16; ++r) sXw[r * 33 + lane] = buf[r];
        __syncwarp();
        if (c < 3) {
            #pragma unroll
            for (int r = 0; r < 16; ++r)
                buf[r] = xb[r * E_DIM + (c + 1) * 32 + lane];
        }
        int eb = e_off + c * 32 + hh * 16;
        #pragma unroll
        for (int e2 = 0; e2 < 16; ++e2) {
            float xv = sXw[rr * 33 + hh * 16 + e2];
            const float4 w0 = *(const float4*)&sW[(eb + e2) * 16 + 0];
            const float4 w1 = *(const float4*)&sW[(eb + e2) * 16 + 4];
            const float4 w2 = *(const float4*)&sW[(eb + e2) * 16 + 8];
            const float4 w3 = *(const float4*)&sW[(eb + e2) * 16 + 12];
            acc[0]  += xv * w0.x;  acc[1]  += xv * w0.y;
            acc[2]  += xv * w0.z;  acc[3]  += xv * w0.w;
            acc[4]  += xv * w1.x;  acc[5]  += xv * w1.y;
            acc[6]  += xv * w1.z;  acc[7]  += xv * w1.w;
            acc[8]  += xv * w2.x;  acc[9]  += xv * w2.y;
            acc[10] += xv * w2.z;  acc[11] += xv * w2.w;
            acc[12] += xv * w3.x;  acc[13] += xv * w3.y;
            acc[14] += xv * w3.z;  acc[15] += xv * w3.w;
        }
    }

    __syncthreads();
    float* rw = red + (w * 32 + lane) * 20;
    *(float4*)&rw[0]  = make_float4(acc[0],  acc[1],  acc[2],  acc[3]);
    *(float4*)&rw[4]  = make_float4(acc[4],  acc[5],  acc[6],  acc[7]);
    *(float4*)&rw[8]  = make_float4(acc[8],  acc[9],  acc[10], acc[11]);
    *(float4*)&rw[12] = make_float4(acc[12], acc[13], acc[14], acc[15]);
    __syncthreads();
    {
        int row = tid >> 4, g = tid & 15;
        float s = 0.f;
        #pragma unroll
        for (int w8 = 0; w8 < 8; ++w8)
            s += red[(w8 * 32 + row) * 20 + g] + red[(w8 * 32 + 16 + row) * 20 + g];
        g_part[sl][g][r0 + row] = s;
    }
}

// =================================================================
// Kernel 2: reduce partials + bias, shuffle scans, tile max, E.
// =================================================================
__device__ __forceinline__ float lsig(float x) {
    float m = fminf(x, 0.f);
    return m - log1pf(expf(-fabsf(x)));
}

__global__ void scan_kernel(const float* __restrict__ bi_p,
                            const float* __restrict__ bf_p) {
    int h = blockIdx.x;
    int t = threadIdx.x;
    int lane = t & 31, wid = t >> 5;
    __shared__ float wsum[32], wmax[32], tmax[32];

    float bi = bi_p[h], bf = bf_p[h];
    float i0 = bi, i1 = bi, f0 = bf, f1 = bf;
    #pragma unroll
    for (int sl = 0; sl < 3; ++sl) {
        float2 vi = *(const float2*)&g_part[sl][h][2 * t];
        float2 vf = *(const float2*)&g_part[sl][h + 8][2 * t];
        i0 += vi.x; i1 += vi.y; f0 += vf.x; f1 += vf.y;
    }
    float l0 = lsig(f0), l1 = lsig(f1);

    float inc = l0 + l1;
    #pragma unroll
    for (int o = 1; o < 32; o <<= 1) {
        float n = __shfl_up_sync(0xffffffffu, inc, o);
        if (lane >= o) inc += n;
    }
    if (lane == 31) wsum[wid] = inc;
    __syncthreads();
    if (t < 32) {
        float v2 = wsum[t];
        #pragma unroll
        for (int o = 1; o < 32; o <<= 1) {
            float n = __shfl_up_sync(0xffffffffu, v2, o);
            if (t >= o) v2 += n;
        }
        wsum[t] = v2;
    }
    __syncthreads();
    float base = wid ? wsum[wid - 1] : 0.f;
    float cum1 = base + inc;
    float cum0 = cum1 - l1;

    float a0 = i0 - cum0, a1 = i1 - cum1;

    float pm = fmaxf(a0, a1);
    float incm = pm;
    #pragma unroll
    for (int o = 1; o < 32; o <<= 1) {
        float n = __shfl_up_sync(0xffffffffu, incm, o);
        if (lane >= o) incm = fmaxf(incm, n);
    }
    if (lane == 31) wmax[wid] = incm;
    __syncthreads();
    if (t < 32) {
        float v2 = wmax[t];
        #pragma unroll
        for (int o = 1; o < 32; o <<= 1) {
            float n = __shfl_up_sync(0xffffffffu, v2, o);
            if (t >= o) v2 = fmaxf(v2, n);
        }
        wmax[t] = v2;
    }
    __syncthreads();
    float basem = wid ? wmax[wid - 1] : -3.4e38f;
    float prev  = __shfl_up_sync(0xffffffffu, incm, 1);
    float exw   = lane ? prev : -3.4e38f;
    float M0 = fmaxf(fmaxf(basem, exw), a0);
    float M1 = fmaxf(M0, a1);
    g_M[h][2 * t]      = M0;
    g_M[h][2 * t + 1]  = M1;
    g_n2[h][2 * t]     = expf(-(cum0 + M0));
    g_n2[h][2 * t + 1] = expf(-(cum1 + M1));

    float mx = pm;
    #pragma unroll
    for (int off = 16; off > 0; off >>= 1)
        mx = fmaxf(mx, __shfl_xor_sync(0xffffffffu, mx, off));
    if (lane == 0) tmax[wid] = mx;
    __syncthreads();
    float T = fmaxf(tmax[wid & ~1], tmax[wid | 1]);
    if ((wid & 1) == 0 && lane == 0) g_T[h][wid >> 1] = T;
    g_E[h][2 * t]     = expf(a0 - T);
    g_E[h][2 * t + 1] = expf(a1 - T);
}

// =================================================================
// Kernel 2.5: prepass — K*E and V to fp16. grid 256 x 256 thr.
// =================================================================
__global__ void prep_kernel(const float* __restrict__ k,
                            const float* __restrict__ v) {
    int tid = threadIdx.x;
    int c4 = tid * 4;
    int h = tid >> 5;
    int r0 = blockIdx.x * 8;
    #pragma unroll
    for (int rr = 0; rr < 8; ++rr) {
        int row = r0 + rr;
        float e = g_E[h][row];
        float4 k4 = *(const float4*)&k[row * E_DIM + c4];
        __half2 ka = __floats2half2_rn(k4.x * e, k4.y * e);
        __half2 kb = __floats2half2_rn(k4.z * e, k4.w * e);
        *(uint2*)&g_kh[row * E_DIM + c4] = make_uint2(*(unsigned*)&ka, *(unsigned*)&kb);
        float4 v4 = *(const float4*)&v[row * E_DIM + c4];
        __half2 va = __floats2half2_rn(v4.x, v4.y);
        __half2 vb = __floats2half2_rn(v4.z, v4.w);
        *(uint2*)&g_vh[row * E_DIM + c4] = make_uint2(*(unsigned*)&va, *(unsigned*)&vb);
    }
}

// =================================================================
// Kernel 3: FA2-style attention — register-resident P.
// 256 thr, 8 warps, warp = m16 x full j128. No P smem, no QK->PV
// barrier. cp.async double-buffered K/V. Q in registers.
// =================================================================
#define STH 136
#define TILE_HALFS (128 * STH)
#define TILE_BYTES (TILE_HALFS * 2)   // 34816

__global__ void __launch_bounds__(256, 1)
attn_kernel(const float* __restrict__ q) {
    extern __shared__ __half smem_h[];
    __half* Qs = smem_h;                     // [128][STH]
    __half* Kb = smem_h + TILE_HALFS;        // 2 buffers
    __half* Vb = smem_h + 3 * TILE_HALFS;    // 2 buffers
    float* sMq = (float*)(smem_h + 5 * TILE_HALFS);  // [128]
    float* sR  = sMq + 128;                          // [128]

    int h    = blockIdx.y;
    int ib   = blockIdx.x;
    int tid  = threadIdx.x;
    int wid  = tid >> 5, lane = tid & 31;
    int g    = lane >> 2, tig = lane & 3;

    unsigned kb_u32 = (unsigned)__cvta_generic_to_shared(Kb);
    unsigned vb_u32 = (unsigned)__cvta_generic_to_shared(Vb);
    unsigned vsm_lane;
    {
        int sel = lane >> 3, l8 = lane & 7;
        vsm_lane = (unsigned)(((((sel & 1) * 8 + l8) * STH) + (sel >> 1) * 8) * 2);
    }

    const float qscale = 0.08838834764831845f;   // 1/sqrt(128)

    #pragma unroll 1
    for (int it = 0; it < 2; ++it) {
        int qt   = it ? ib : (15 - ib);
        int half = it ? 0 : 1;
        int nj   = qt + 1;
        int jlo  = half ? (nj >> 1) : 0;
        int jhi  = half ? nj : (nj >> 1);
        int i0   = qt * 128;

        __syncthreads();   // prior item's reads done before buffer/Qs reuse

        // issue first K/V tile into buffer 0
        if (jlo < jhi) {
            const __half* ks = g_kh + (size_t)(jlo * 128) * E_DIM + h * DH;
            const __half* vs = g_vh + (size_t)(jlo * 128) * E_DIM + h * DH;
            #pragma unroll
            for (int t = 0; t < 8; ++t) {
                int chunk = tid + t * 256;
                int row = chunk >> 4, c16 = chunk & 15;
                cpa16(kb_u32 + row * 272 + c16 * 16, ks + row * E_DIM + c16 * 8);
                cpa16(vb_u32 + row * 272 + c16 * 16, vs + row * E_DIM + c16 * 8);
            }
            cpa_commit();
        }

        // stage Q (fp32 -> half, pre-scaled)
        for (int idx = tid; idx < 128 * 32; idx += 256) {
            int i = idx >> 5, c4 = (idx & 31) * 4;
            float4 t4 = *(const float4*)&q[(i0 + i) * E_DIM + h * DH + c4];
            __half2 h01 = __floats2half2_rn(t4.x * qscale, t4.y * qscale);
            __half2 h23 = __floats2half2_rn(t4.z * qscale, t4.w * qscale);
            *(uint2*)&Qs[i * STH + c4] = make_uint2(*(unsigned*)&h01, *(unsigned*)&h23);
        }
        if (tid < 128) sMq[tid] = g_M[h][i0 + tid];
        __syncthreads();

        // load Q fragments into registers (held across the j loop)
        unsigned Qr[8][4];
        int r0q = wid * 16 + g;
        #pragma unroll
        for (int ks = 0; ks < 8; ++ks) {
            int d0 = ks * 16;
            Qr[ks][0] = *(const unsigned*)&Qs[r0q * STH + d0 + 2 * tig];
            Qr[ks][1] = *(const unsigned*)&Qs[(r0q + 8) * STH + d0 + 2 * tig];
            Qr[ks][2] = *(const unsigned*)&Qs[r0q * STH + d0 + 8 + 2 * tig];
            Qr[ks][3] = *(const unsigned*)&Qs[(r0q + 8) * STH + d0 + 8 + 2 * tig];
        }

        float Oa[16][4];
        #pragma unroll
        for (int nt = 0; nt < 16; ++nt)
            #pragma unroll
            for (int c = 0; c < 4; ++c) Oa[nt][c] = 0.f;
        float rs0 = 0.f, rs1 = 0.f;

        int cur = 0;
        for (int jt = jlo; jt < jhi; ++jt) {
            int j0 = jt * 128;
            if (jt + 1 < jhi) {
                int nb = cur ^ 1;
                const __half* ks = g_kh + (size_t)((jt + 1) * 128) * E_DIM + h * DH;
                const __half* vs = g_vh + (size_t)((jt + 1) * 128) * E_DIM + h * DH;
                #pragma unroll
                for (int t = 0; t < 8; ++t) {
                    int chunk = tid + t * 256;
                    int row = chunk >> 4, c16 = chunk & 15;
                    cpa16(kb_u32 + nb * TILE_BYTES + row * 272 + c16 * 16,
                          ks + row * E_DIM + c16 * 8);
                    cpa16(vb_u32 + nb * TILE_BYTES + row * 272 + c16 * 16,
                          vs + row * E_DIM + c16 * 8);
                }
                cpa_commit();
                cpa_wait<1>();
            } else {
                cpa_wait<0>();
            }
            if (tid < 128) sR[tid] = __expf(g_T[h][jt] - sMq[tid]);
            __syncthreads();   // buffer + sR visible

            const __half* Kc = Kb + cur * TILE_HALFS;

            // ---- QK^T: warp m16 x n128, acc in regs ----
            float acc[16][4];
            #pragma unroll
            for (int nt = 0; nt < 16; ++nt)
                #pragma unroll
                for (int c = 0; c < 4; ++c) acc[nt][c] = 0.f;

            #pragma unroll
            for (int nt = 0; nt < 16; ++nt) {
                int jb = nt * 8 + g;
                #pragma unroll
                for (int ks = 0; ks < 8; ++ks) {
                    unsigned b[2];
                    b[0] = *(const unsigned*)&Kc[jb * STH + ks * 16 + 2 * tig];
                    b[1] = *(const unsigned*)&Kc[jb * STH + ks * 16 + 8 + 2 * tig];
                    mma16(acc[nt], Qr[ks], b);
                }
            }

            // ---- apply R, mask, rowsum, pack P to A-fragments ----
            float Rl = sR[wid * 16 + g];
            float Rh = sR[wid * 16 + 8 + g];
            bool diag = (jt == qt);
            int iglo = i0 + wid * 16 + g, ighi = iglo + 8;
            unsigned A[8][4];
            #pragma unroll
            for (int nt = 0; nt < 16; ++nt) {
                int jg = j0 + nt * 8 + 2 * tig;
                float p0 = acc[nt][0] * Rl;
                float p1 = acc[nt][1] * Rl;
                float p2 = acc[nt][2] * Rh;
                float p3 = acc[nt][3] * Rh;
                if (diag) {
                    if (jg     > iglo) p0 = 0.f;
                    if (jg + 1 > iglo) p1 = 0.f;
                    if (jg     > ighi) p2 = 0.f;
                    if (jg + 1 > ighi) p3 = 0.f;
                }
                rs0 += p0 + p1;
                rs1 += p2 + p3;
                __half2 h01 = __floats2half2_rn(p0, p1);
                __half2 h23 = __floats2half2_rn(p2, p3);
                A[nt >> 1][(nt & 1) * 2 + 0] = *(unsigned*)&h01;
                A[nt >> 1][(nt & 1) * 2 + 1] = *(unsigned*)&h23;
            }

            // ---- P @ V: O += A * V, V frags via ldmatrix.trans ----
            unsigned vbase = vb_u32 + cur * TILE_BYTES + vsm_lane;
            #pragma unroll
            for (int jk = 0; jk < 8; ++jk) {
                #pragma unroll
                for (int dp = 0; dp < 8; ++dp) {
                    unsigned r4[4];
                    ldsm4t(r4, vbase + (unsigned)((jk * 16 * STH + dp * 16) * 2));
                    unsigned b0[2] = {r4[0], r4[1]};
                    unsigned b1[2] = {r4[2], r4[3]};
                    mma16(Oa[2 * dp],     A[jk], b0);
                    mma16(Oa[2 * dp + 1], A[jk], b1);
                }
            }
            __syncthreads();   // cur-buffer reads done before reuse
            cur ^= 1;
        }

        // ---- epilogue: per-warp complete rowsums + partial O ----
        rs0 += __shfl_xor_sync(0xffffffffu, rs0, 1);
        rs0 += __shfl_xor_sync(0xffffffffu, rs0, 2);
        rs1 += __shfl_xor_sync(0xffffffffu, rs1, 1);
        rs1 += __shfl_xor_sync(0xffffffffu, rs1, 2);
        int grow0 = i0 + wid * 16 + g, grow1 = grow0 + 8;
        if (tig == 0) {
            g_rsp[half][h][grow0] = rs0;
            g_rsp[half][h][grow1] = rs1;
        }
        float* Op = g_Op[half];
        #pragma unroll
        for (int nt = 0; nt < 16; ++nt) {
            *(float2*)&Op[grow0 * E_DIM + h * DH + nt * 8 + 2 * tig]
                = make_float2(Oa[nt][0], Oa[nt][1]);
            *(float2*)&Op[grow1 * E_DIM + h * DH + nt * 8 + 2 * tig]
                = make_float2(Oa[nt][2], Oa[nt][3]);
        }
    }
}

// =================================================================
// Kernel 4: fixup — 4 rows per block (best measured). grid 512.
// =================================================================
__global__ void fixup_kernel(const float* __restrict__ lnsc,
                             float* __restrict__ out) {
    int ib = blockIdx.x;
    int h = threadIdx.x >> 5, lane = threadIdx.x & 31;
    int c4 = lane * 4;

    float4 p0[4], p1[4];
    float rsum[4], n2v[4];
    #pragma unroll
    for (int rr = 0; rr < 4; ++rr) {
        int i = ib * 4 + rr;
        int base = i * E_DIM + h * DH + c4;
        p0[rr] = *(const float4*)&g_Op[0][base];
        p1[rr] = *(const float4*)&g_Op[1][base];
        rsum[rr] = g_rsp[0][h][i] + g_rsp[1][h][i];
        n2v[rr]  = g_n2[h][i];
    }
    float4 gl = *(const float4*)&lnsc[h * DH + c4];

    float x[4][4], s[4], s2[4];
    #pragma unroll
    for (int rr = 0; rr < 4; ++rr) {
        float denom = fmaxf(fabsf(rsum[rr]), n2v[rr]) + EPS_F;
        float invd = 1.f / denom;
        x[rr][0] = (p0[rr].x + p1[rr].x) * invd;
        x[rr][1] = (p0[rr].y + p1[rr].y) * invd;
        x[rr][2] = (p0[rr].z + p1[rr].z) * invd;
        x[rr][3] = (p0[rr].w + p1[rr].w) * invd;
        s[rr]  = x[rr][0] + x[rr][1] + x[rr][2] + x[rr][3];
        s2[rr] = x[rr][0] * x[rr][0] + x[rr][1] * x[rr][1]
               + x[rr][2] * x[rr][2] + x[rr][3] * x[rr][3];
    }
    #pragma unroll
    for (int o = 16; o > 0; o >>= 1) {
        #pragma unroll
        for (int rr = 0; rr < 4; ++rr) {
            s[rr]  += __shfl_xor_sync(0xffffffffu, s[rr],  o);
            s2[rr] += __shfl_xor_sync(0xffffffffu, s2[rr], o);
        }
    }
    #pragma unroll
    for (int rr = 0; rr < 4; ++rr) {
        float mean = s[rr] * (1.f / 128.f);
        float rstd = rsqrtf(s2[rr] * (1.f / 128.f) - mean * mean + EPS_F);
        int base = (ib * 4 + rr) * E_DIM + h * DH + c4;
        float4 o4;
        o4.x = (x[rr][0] - mean) * rstd * gl.x;
        o4.y = (x[rr][1] - mean) * rstd * gl.y;
        o4.z = (x[rr][2] - mean) * rstd * gl.z;
        o4.w = (x[rr][3] - mean) * rstd * gl.w;
        *(float4*)&out[base] = o4;
    }
}

// =================================================================
extern "C" void kernel_launch(void* const* d_in, const int* in_sizes, int n_in,
                              void* d_out, int out_size) {
    const float* q    = (const float*)d_in[0];
    const float* k    = (const float*)d_in[1];
    const float* v    = (const float*)d_in[2];
    const float* Wi   = (const float*)d_in[3];
    const float* bi   = (const float*)d_in[4];
    const float* Wf   = (const float*)d_in[5];
    const float* bf   = (const float*)d_in[6];
    const float* lnsc = (const float*)d_in[7];
    float* out = (float*)d_out;

    const int gate_smem = (1024 * 16 + 8 * 16 * 33 + 8 * 32 * 20) * 4;  // 102912 B
    const int attn_smem = 5 * TILE_BYTES + 1024;                        // 175104 B

    cudaFuncSetAttribute(gate_kernel, cudaFuncAttributeMaxDynamicSharedMemorySize, gate_smem);
    cudaFuncSetAttribute(attn_kernel, cudaFuncAttributeMaxDynamicSharedMemorySize, attn_smem);

    gate_kernel<<<dim3(128, 3), 256, gate_smem>>>(q, k, v, Wi, Wf);
    scan_kernel<<<8, 1024>>>(bi, bf);
    prep_kernel<<<256, 256>>>(k, v);
    attn_kernel<<<dim3(16, NH), 256, attn_smem>>>(q);
    fixup_kernel<<<S_LEN / 4, 256>>>(lnsc, out);
}